// round 17
// baseline (speedup 1.0000x reference)
#include <cuda_runtime.h>
#include <cstdint>

#define N_NODES 100000
#define N_EDGES 640000
#define N_FEAT 128
#define N_CLASSES 16
#define NB_NODES 391               // ceil(N_NODES/256)
#define EDGES_PER_BLOCK ((N_EDGES + NB_NODES - 1) / NB_NODES)   // 1637

// Scratch (no allocations allowed). Invariants at csr_gather entry:
// g_cnt holds the in-degree histogram; counters zeroed by proj (stream-
// ordered before csr_gather). g_cnt re-zeroed in phase C for the next call.
__device__ float4 g_y[N_NODES * 4];        // x @ W_l^T   (16 floats/node)
__device__ float4 g_z[N_NODES * 4];        // x @ W_r^T + b_l
__device__ int    g_cnt[N_NODES];          // histogram -> scatter cursor
__device__ int    g_start[N_NODES];        // CSR start offsets
__device__ int    g_blocksum[NB_NODES];    // per-block degree sums
__device__ int    g_ctrS, g_ctrA, g_ctrB;  // grid-barrier counters
__device__ int    g_csr_src[N_EDGES];      // src id per CSR slot

// Packed fp32x2 FMA (sm_103a native)
#define FMA_F32X2(d, a, b, c) \
    asm("fma.rn.f32x2 %0, %1, %2, %3;" : "=l"(d) : "l"(a), "l"(b), "l"(c))

__device__ __forceinline__ unsigned long long pack2(float lo, float hi) {
    unsigned long long r;
    asm("mov.b64 %0, {%1, %2};" : "=l"(r) : "f"(lo), "f"(hi));
    return r;
}
__device__ __forceinline__ float sum2(unsigned long long v) {
    float lo, hi;
    asm("mov.b64 {%0, %1}, %2;" : "=f"(lo), "=f"(hi) : "l"(v));
    return lo + hi;
}

// Block-local dtype detect: 64 threads test one 8B word each.
__device__ __forceinline__ int detect_is64_block(const void* ei, int tid,
                                                 int* s_flag) {
    if (tid == 0) *s_flag = 0;
    __syncthreads();
    if (tid < 64) {
        unsigned long long w = __ldg(&((const unsigned long long*)ei)[tid]);
        if (w >= (1ULL << 32)) *s_flag = 1;     // benign same-value race
    }
    __syncthreads();
    return !(*s_flag);
}

__device__ __forceinline__ int load_dst(const void* ei, int e, int is64) {
    if (is64) return (int)__ldg(&((const long long*)ei)[N_EDGES + e]);
    return __ldg(&((const int*)ei)[N_EDGES + e]);
}
__device__ __forceinline__ int load_src(const void* ei, int e, int is64) {
    if (is64) return (int)__ldg(&((const long long*)ei)[e]);
    return __ldg(&((const int*)ei)[e]);
}

// Spin with HW sleep to avoid hammering the counter line from 391 blocks.
__device__ __forceinline__ void spin_until(volatile int* ctr, int target) {
    while (*ctr < target) __nanosleep(64);
}

// Grid barrier arrive+wait (all 391 blocks resident in wave 1).
__device__ __forceinline__ void grid_barrier(int* ctr, int tid) {
    __threadfence();
    __syncthreads();
    if (tid == 0) {
        atomicAdd(ctr, 1);
        spin_until((volatile int*)ctr, NB_NODES);
        __threadfence();
    }
    __syncthreads();
}

// ---------------------------------------------------------------------------
// Projection + fused in-degree histogram (g_cnt == 0 at entry; counters
// for the csr kernel are reset here, stream-ordered before their use).
// ---------------------------------------------------------------------------
#define CHUNK_F4 8
#define TILE_STRIDE 9

__global__ __launch_bounds__(256) void proj_kernel(
    const float* __restrict__ x,
    const float* __restrict__ Wl,
    const float* __restrict__ bl,
    const float* __restrict__ Wr,
    const void* __restrict__ ei)
{
    __shared__ float4 sWl[N_CLASSES * (N_FEAT / 4)];   // 8 KB
    __shared__ float4 sWr[N_CLASSES * (N_FEAT / 4)];   // 8 KB
    __shared__ float  sb[N_CLASSES];
    __shared__ float4 tile[256 * TILE_STRIDE];         // 36 KB
    __shared__ int    s_flag;

    int tid = threadIdx.x;
    if (blockIdx.x == 0 && tid == 0) { g_ctrS = 0; g_ctrA = 0; g_ctrB = 0; }
    int is64 = detect_is64_block(ei, tid, &s_flag);

    const float4* Wl4 = (const float4*)Wl;
    const float4* Wr4 = (const float4*)Wr;
    for (int i = tid; i < N_CLASSES * (N_FEAT / 4); i += 256) {
        sWl[i] = Wl4[i];
        sWr[i] = Wr4[i];
    }
    if (tid < N_CLASSES) sb[tid] = bl[tid];

    // Fused histogram slice (drains under the FMA-bound loop below).
    {
        int e0 = blockIdx.x * EDGES_PER_BLOCK;
        int e1 = min(e0 + EDGES_PER_BLOCK, N_EDGES);
        for (int e = e0 + tid; e < e1; e += 256) {
            atomicAdd(&g_cnt[load_dst(ei, e, is64)], 1);
        }
    }

    int base = blockIdx.x * 256;
    int node = base + tid;
    bool active = (node < N_NODES);

    unsigned long long accl[N_CLASSES];
    unsigned long long accr[N_CLASSES];
#pragma unroll
    for (int c = 0; c < N_CLASSES; c++) { accl[c] = 0ULL; accr[c] = 0ULL; }

    const float4* x4 = (const float4*)x;

    for (int ch = 0; ch < N_FEAT / (4 * CHUNK_F4); ch++) {
        __syncthreads();
#pragma unroll
        for (int i = 0; i < CHUNK_F4; i++) {
            int f = tid + i * 256;
            int n = f >> 3;
            int j = f & 7;
            int gn = base + n;
            if (gn >= N_NODES) gn = N_NODES - 1;
            tile[n * TILE_STRIDE + j] =
                x4[(size_t)gn * (N_FEAT / 4) + ch * CHUNK_F4 + j];
        }
        __syncthreads();

#pragma unroll
        for (int j = 0; j < CHUNK_F4; j++) {
            float4 xv = tile[tid * TILE_STRIDE + j];
            unsigned long long xlo = pack2(xv.x, xv.y);
            unsigned long long xhi = pack2(xv.z, xv.w);
            int k = ch * CHUNK_F4 + j;
#pragma unroll
            for (int c = 0; c < N_CLASSES; c++) {
                float4 wl = sWl[c * (N_FEAT / 4) + k];
                FMA_F32X2(accl[c], xlo, pack2(wl.x, wl.y), accl[c]);
                FMA_F32X2(accl[c], xhi, pack2(wl.z, wl.w), accl[c]);
                float4 wr = sWr[c * (N_FEAT / 4) + k];
                FMA_F32X2(accr[c], xlo, pack2(wr.x, wr.y), accr[c]);
                FMA_F32X2(accr[c], xhi, pack2(wr.z, wr.w), accr[c]);
            }
        }
    }

    if (active) {
#pragma unroll
        for (int c4 = 0; c4 < 4; c4++) {
            float4 vy, vz;
            vy.x = sum2(accl[c4 * 4 + 0]);
            vy.y = sum2(accl[c4 * 4 + 1]);
            vy.z = sum2(accl[c4 * 4 + 2]);
            vy.w = sum2(accl[c4 * 4 + 3]);
            vz.x = sum2(accr[c4 * 4 + 0]) + sb[c4 * 4 + 0];
            vz.y = sum2(accr[c4 * 4 + 1]) + sb[c4 * 4 + 1];
            vz.z = sum2(accr[c4 * 4 + 2]) + sb[c4 * 4 + 2];
            vz.w = sum2(accr[c4 * 4 + 3]) + sb[c4 * 4 + 3];
            g_y[node * 4 + c4] = vy;
            g_z[node * 4 + c4] = vz;
        }
    }
}

// ---------------------------------------------------------------------------
// Fused CSR build + gather + finalize. 391 blocks x 256 threads, all
// resident in wave 1 (min-blocks=3 caps regs -> 3 blocks/SM, 444 >= 391),
// so grid barriers cannot deadlock.
// Phase A: per-block scan + blocksum barrier + offsets/cursors.
// Phase B: scatter this block's 1637-edge slice into CSR.
// Phase C: gather+finalize, 2 interleaved chains x 2 passes (MLP 2,
//          bounded register pressure under the min-blocks=3 cap).
// ---------------------------------------------------------------------------
__global__ __launch_bounds__(256, 3) void csr_gather_kernel(
    const void* __restrict__ ei, float* __restrict__ out)
{
    __shared__ int s[256];
    __shared__ int red[256];
    __shared__ int s_flag;

    int tid = threadIdx.x;
    int bid = blockIdx.x;
    int is64 = detect_is64_block(ei, tid, &s_flag);

    // ---- Phase A: exclusive scan ----
    int i = bid * 256 + tid;
    int v = (i < N_NODES) ? g_cnt[i] : 0;
    s[tid] = v;
    __syncthreads();
#pragma unroll
    for (int off = 1; off < 256; off <<= 1) {
        int t = (tid >= off) ? s[tid - off] : 0;
        __syncthreads();
        s[tid] += t;
        __syncthreads();
    }
    int local_excl = s[tid] - v;

    if (tid == 255) {
        g_blocksum[bid] = s[255];
        __threadfence();
        atomicAdd(&g_ctrS, 1);
    }
    if (tid == 0) {
        spin_until((volatile int*)&g_ctrS, NB_NODES);
        __threadfence();
    }
    __syncthreads();

    int part = 0;
    for (int p = tid; p < bid; p += 256) part += g_blocksum[p];
    red[tid] = part;
    __syncthreads();
#pragma unroll
    for (int off = 128; off > 0; off >>= 1) {
        if (tid < off) red[tid] += red[tid + off];
        __syncthreads();
    }
    int boff = red[0];

    if (i < N_NODES) {
        int st = local_excl + boff;
        g_start[i] = st;
        g_cnt[i] = st;                              // scatter cursor
    }
    grid_barrier(&g_ctrA, tid);                     // cursors visible

    // ---- Phase B: scatter ----
    {
        int e0 = bid * EDGES_PER_BLOCK;
        int e1 = min(e0 + EDGES_PER_BLOCK, N_EDGES);
        for (int e = e0 + tid; e < e1; e += 256) {
            int src = load_src(ei, e, is64);
            int dst = load_dst(ei, e, is64);
            int pos = atomicAdd(&g_cnt[dst], 1);
            g_csr_src[pos] = src;
        }
    }
    grid_barrier(&g_ctrB, tid);                     // CSR complete

    // ---- Phase C: gather + finalize (2 chains x 2 passes) ----
    int base_t = bid * 1024 + tid;                  // unit u: base_t + u*256
    int q = base_t & 3;

#pragma unroll
    for (int pass = 0; pass < 2; pass++) {
        int t0 = base_t + (pass * 2 + 0) * 256;
        int t1 = base_t + (pass * 2 + 1) * 256;
        bool ok0 = (t0 < N_NODES * 4);
        bool ok1 = (t1 < N_NODES * 4);
        int n0 = t0 >> 2, n1 = t1 >> 2;

        int s0 = 0, e0 = 0, s1 = 0, e1 = 0;
        if (ok0) {
            s0 = __ldg(&g_start[n0]);
            e0 = (n0 + 1 < N_NODES) ? __ldg(&g_start[n0 + 1]) : N_EDGES;
            if (q == 0) g_cnt[n0] = 0;              // restore invariant
        }
        if (ok1) {
            s1 = __ldg(&g_start[n1]);
            e1 = (n1 + 1 < N_NODES) ? __ldg(&g_start[n1 + 1]) : N_EDGES;
            if (q == 0) g_cnt[n1] = 0;              // restore invariant
        }
        int d0 = e0 - s0, d1 = e1 - s1;

        float4 a0 = make_float4(0.f, 0.f, 0.f, 0.f);
        float4 a1 = make_float4(0.f, 0.f, 0.f, 0.f);

        while (s0 < e0 || s1 < e1) {
            bool c0 = (s0 < e0), c1 = (s1 < e1);
            int r0 = 0, r1 = 0;
            if (c0) r0 = __ldg(&g_csr_src[s0]);
            if (c1) r1 = __ldg(&g_csr_src[s1]);
            if (c0) {
                float4 vv = g_y[r0 * 4 + q];
                a0.x += vv.x; a0.y += vv.y; a0.z += vv.z; a0.w += vv.w;
                s0++;
            }
            if (c1) {
                float4 vv = g_y[r1 * 4 + q];
                a1.x += vv.x; a1.y += vv.y; a1.z += vv.z; a1.w += vv.w;
                s1++;
            }
        }

        if (ok0) {
            float inv = __fdividef(1.0f, fmaxf((float)d0, 1.0f));
            float4 z = g_z[t0];
            float4 o;
            o.x = fmaxf(fmaf(a0.x, inv, z.x), 0.0f);
            o.y = fmaxf(fmaf(a0.y, inv, z.y), 0.0f);
            o.z = fmaxf(fmaf(a0.z, inv, z.z), 0.0f);
            o.w = fmaxf(fmaf(a0.w, inv, z.w), 0.0f);
            ((float4*)out)[t0] = o;
        }
        if (ok1) {
            float inv = __fdividef(1.0f, fmaxf((float)d1, 1.0f));
            float4 z = g_z[t1];
            float4 o;
            o.x = fmaxf(fmaf(a1.x, inv, z.x), 0.0f);
            o.y = fmaxf(fmaf(a1.y, inv, z.y), 0.0f);
            o.z = fmaxf(fmaf(a1.z, inv, z.z), 0.0f);
            o.w = fmaxf(fmaf(a1.w, inv, z.w), 0.0f);
            ((float4*)out)[t1] = o;
        }
    }
}

extern "C" void kernel_launch(void* const* d_in, const int* in_sizes, int n_in,
                              void* d_out, int out_size) {
    const float* x  = (const float*)d_in[0];
    const void*  ei = d_in[1];
    const float* Wl = (const float*)d_in[2];
    const float* bl = (const float*)d_in[3];
    const float* Wr = (const float*)d_in[4];
    float* out = (float*)d_out;

    proj_kernel<<<NB_NODES, 256>>>(x, Wl, bl, Wr, ei);
    csr_gather_kernel<<<NB_NODES, 256>>>(ei, out);
}